// round 15
// baseline (speedup 1.0000x reference)
#include <cuda_runtime.h>
#include <cuda_fp16.h>
#include <cstdint>

#define T_SEQ   2048
#define D_MODEL 1024
#define N_HEADS 16
#define D_HEAD  64
#define B_SZ    2
#define N_TOK   (B_SZ * T_SEQ)   // 4096

// fp16 scratch (device globals: allocation-free per harness rules)
__device__ __half g_xh  [(size_t)N_TOK * D_MODEL];        // x in fp16
__device__ __half g_wqh [(size_t)D_MODEL * 3 * D_MODEL];  // w_qkv fp16
__device__ __half g_woh [(size_t)D_MODEL * D_MODEL];      // w_out fp16
__device__ __half g_qkvh[(size_t)N_TOK * 3 * D_MODEL];    // qkv (Q pre-scaled 1/8)
__device__ __half g_atth[(size_t)N_TOK * D_MODEL];        // attention out fp16

// ---------------------------------------------------------------------------
// helpers
// ---------------------------------------------------------------------------
__device__ __forceinline__ uint32_t pack_f16x2(float lo, float hi) {
    uint32_t r;
    asm("cvt.rn.f16x2.f32 %0, %1, %2;" : "=r"(r) : "f"(hi), "f"(lo));
    return r;
}

__device__ __forceinline__ void mma_f16(float c[4], const uint32_t a[4], const uint32_t b[2]) {
    asm volatile(
        "mma.sync.aligned.m16n8k16.row.col.f32.f16.f16.f32 "
        "{%0,%1,%2,%3}, {%4,%5,%6,%7}, {%8,%9}, {%0,%1,%2,%3};\n"
        : "+f"(c[0]), "+f"(c[1]), "+f"(c[2]), "+f"(c[3])
        : "r"(a[0]), "r"(a[1]), "r"(a[2]), "r"(a[3]), "r"(b[0]), "r"(b[1]));
}

__device__ __forceinline__ uint32_t smem_u32(const void* p) {
    uint32_t a;
    asm("{ .reg .u64 t; cvta.to.shared.u64 t, %1; cvt.u32.u64 %0, t; }"
        : "=r"(a) : "l"(p));
    return a;
}

__device__ __forceinline__ void ldsm_x4(uint32_t& r0, uint32_t& r1,
                                        uint32_t& r2, uint32_t& r3, uint32_t addr) {
    asm volatile("ldmatrix.sync.aligned.m8n8.x4.shared.b16 {%0,%1,%2,%3}, [%4];"
                 : "=r"(r0), "=r"(r1), "=r"(r2), "=r"(r3) : "r"(addr));
}
__device__ __forceinline__ void ldsm_x4_t(uint32_t& r0, uint32_t& r1,
                                          uint32_t& r2, uint32_t& r3, uint32_t addr) {
    asm volatile("ldmatrix.sync.aligned.m8n8.x4.trans.shared.b16 {%0,%1,%2,%3}, [%4];"
                 : "=r"(r0), "=r"(r1), "=r"(r2), "=r"(r3) : "r"(addr));
}

__device__ __forceinline__ void cp16(uint32_t dst, const void* src) {
    asm volatile("cp.async.cg.shared.global [%0], [%1], 16;" :: "r"(dst), "l"(src));
}
#define CP_COMMIT() asm volatile("cp.async.commit_group;" ::: "memory")
#define CP_WAIT0()  asm volatile("cp.async.wait_group 0;" ::: "memory")
#define CP_WAIT1()  asm volatile("cp.async.wait_group 1;" ::: "memory")

// ---------------------------------------------------------------------------
// fp32 -> fp16 converter (elementwise, float4 -> 2x f16x2)
// ---------------------------------------------------------------------------
__global__ void cvt_f32_f16_kernel(const float4* __restrict__ in,
                                   uint2* __restrict__ out, int n4)
{
    int i = blockIdx.x * blockDim.x + threadIdx.x;
    if (i < n4) {
        float4 v = in[i];
        out[i] = make_uint2(pack_f16x2(v.x, v.y), pack_f16x2(v.z, v.w));
    }
}

// ---------------------------------------------------------------------------
// fp16-in tensor-core GEMM with fused bias, 3-stage cp.async pipeline.
// (unchanged from round 14)
// ---------------------------------------------------------------------------
#define GWA 12   // A row stride in words (48B)
#define GWB 68   // B row stride in words (272B)

template <int M, int N, int K, int OUTH>
__global__ void __launch_bounds__(256, 2) gemm_f16_kernel(
    const __half* __restrict__ A, const __half* __restrict__ B,
    const float* __restrict__ bias, void* __restrict__ Cout, int q_cols)
{
    __shared__ __align__(16) uint32_t As[3][128 * GWA];
    __shared__ __align__(16) uint32_t Bs[3][16 * GWB];

    const int tid  = threadIdx.x;
    const int warp = tid >> 5;
    const int lane = tid & 31;
    const int g    = lane >> 2;
    const int tg   = lane & 3;
    const int wm   = (warp >> 1) * 32;
    const int wn   = (warp & 1) * 64;

    const int bm = blockIdx.y;
    const int bn = blockIdx.x;

    const __half* Ab = A + (size_t)bm * 128 * K;
    const __half* Bb = B + (size_t)bn * 128;

    const int a_r = tid >> 1, a_c = tid & 1;
    const int b_r = tid >> 4, b_c = tid & 15;

    float acc[2][8][4];
    #pragma unroll
    for (int i = 0; i < 2; ++i)
        #pragma unroll
        for (int j = 0; j < 8; ++j)
            #pragma unroll
            for (int q = 0; q < 4; ++q) acc[i][j][q] = 0.0f;

    const int a_row   = (lane & 7) + ((lane >> 3) & 1) * 8;
    const int a_chunk = (lane >> 4) & 1;
    const int b_k     = (lane & 7) + ((lane >> 3) & 1) * 8;
    const int b_nc8   = ((lane >> 4) & 1) * 8;

    const int NKT = K / 16;

    #define GISSUE(st, kt) do {                                                   \
        uint32_t ad = smem_u32(&As[st][0]) + a_r * 48 + a_c * 16;                 \
        cp16(ad, Ab + (size_t)a_r * K + (kt) + a_c * 8);                          \
        uint32_t bd = smem_u32(&Bs[st][0]) + b_r * 272 + b_c * 16;                \
        cp16(bd, Bb + (size_t)((kt) + b_r) * N + b_c * 8);                        \
        CP_COMMIT();                                                              \
    } while (0)

    GISSUE(0, 0);
    GISSUE(1, 16);

    for (int kt = 0; kt < NKT; ++kt) {
        const int cur = kt % 3;
        if (kt + 1 < NKT) CP_WAIT1(); else CP_WAIT0();
        __syncthreads();
        if (kt + 2 < NKT) GISSUE((kt + 2) % 3, (kt + 2) * 16);

        const uint32_t aBase = smem_u32(&As[cur][0]);
        const uint32_t bBase = smem_u32(&Bs[cur][0]);
        uint32_t a[2][4], b[8][2];
        #pragma unroll
        for (int mm = 0; mm < 2; ++mm) {
            uint32_t addr = aBase + (wm + mm * 16 + a_row) * 48 + a_chunk * 16;
            ldsm_x4(a[mm][0], a[mm][1], a[mm][2], a[mm][3], addr);
        }
        #pragma unroll
        for (int nc = 0; nc < 4; ++nc) {
            uint32_t addr = bBase + b_k * 272 + (wn + nc * 16 + b_nc8) * 2;
            uint32_t r0, r1, r2, r3;
            ldsm_x4_t(r0, r1, r2, r3, addr);
            b[2 * nc][0]     = r0; b[2 * nc][1]     = r1;
            b[2 * nc + 1][0] = r2; b[2 * nc + 1][1] = r3;
        }
        #pragma unroll
        for (int mm = 0; mm < 2; ++mm)
            #pragma unroll
            for (int nn = 0; nn < 8; ++nn)
                mma_f16(acc[mm][nn], a[mm], b[nn]);
    }
    #undef GISSUE

    #pragma unroll
    for (int mm = 0; mm < 2; ++mm) {
        const int r0 = bm * 128 + wm + mm * 16 + g;
        #pragma unroll
        for (int nn = 0; nn < 8; ++nn) {
            const int c0g = bn * 128 + wn + nn * 8 + 2 * tg;
            float b0 = bias[c0g], b1 = bias[c0g + 1];
            if (OUTH) {
                __half* C = (__half*)Cout;
                float sc = (c0g < q_cols) ? 0.125f : 1.0f;
                *(uint32_t*)(C + (size_t)r0 * N + c0g) =
                    pack_f16x2((acc[mm][nn][0] + b0) * sc, (acc[mm][nn][1] + b1) * sc);
                *(uint32_t*)(C + (size_t)(r0 + 8) * N + c0g) =
                    pack_f16x2((acc[mm][nn][2] + b0) * sc, (acc[mm][nn][3] + b1) * sc);
            } else {
                float* C = (float*)Cout;
                *(float2*)(C + (size_t)r0 * N + c0g) =
                    make_float2(acc[mm][nn][0] + b0, acc[mm][nn][1] + b1);
                *(float2*)(C + (size_t)(r0 + 8) * N + c0g) =
                    make_float2(acc[mm][nn][2] + b0, acc[mm][nn][3] + b1);
            }
        }
    }
}

// ---------------------------------------------------------------------------
// Causal flash attention, fp16 m16n8k16, ldmatrix frags.
// Q-tile 128 (8 warps x 16 rows), K-tile 64, DH=64.
// 2-stage double-buffered K/V via cp.async: loads for kt+1 overlap compute(kt).
// Q staged through both K stages, frags extracted before mainloop.
// ---------------------------------------------------------------------------
#define FWS   36               // K/V row stride in words (144B)
#define FSTGB (64 * 144)       // stage size in bytes (9216)

__global__ void __launch_bounds__(256, 2) flash_attn_f16_kernel()
{
    __shared__ __align__(16) uint32_t Ks[2 * 64 * FWS];
    __shared__ __align__(16) uint32_t Vs[2 * 64 * FWS];

    const int tid  = threadIdx.x;
    const int warp = tid >> 5;           // 0..7
    const int lane = tid & 31;
    const int g    = lane >> 2;
    const int tg   = lane & 3;
    const int qt   = gridDim.x - 1 - blockIdx.x;   // long diagonals first
    const int h    = blockIdx.y;
    const int b    = blockIdx.z;
    const int q0   = qt * 128;
    const int qrow = warp * 16;          // 0..112

    const __half* qkvh = g_qkvh;
    const uint32_t ksBase = smem_u32(Ks);
    const uint32_t vsBase = smem_u32(Vs);

    // ldmatrix lane addressing
    const int k_tok8  = lane & 7;
    const int k_doff  = ((lane >> 3) & 3) * 16;
    const int v_tok   = (lane & 7) + ((lane >> 3) & 1) * 8;
    const int v_dcol8 = ((lane >> 4) & 1) * 8;

    // ---- stage Q (128 rows, pre-scaled) into BOTH Ks stages via cp.async ----
    #pragma unroll
    for (int p = 0; p < 4; ++p) {
        int idx = tid + p * 256;             // 0..1023
        int r = idx >> 3, c = idx & 7;       // row 0..127, 16B chunk
        cp16(ksBase + (r >> 6) * FSTGB + (r & 63) * 144 + c * 16,
             qkvh + (size_t)(b * T_SEQ + q0 + r) * 3072 + h * 64 + c * 8);
    }
    CP_COMMIT(); CP_WAIT0();
    __syncthreads();

    uint32_t aq[4][4];
    {
        const uint32_t qbase = ksBase + (qrow >> 6) * FSTGB;
        const int srow = qrow & 63;
        #pragma unroll
        for (int kc = 0; kc < 2; ++kc) {
            uint32_t addr = qbase + (srow + v_tok) * 144 + kc * 64 + v_dcol8 * 2;
            ldsm_x4(aq[2 * kc][0], aq[2 * kc][1], aq[2 * kc][2], aq[2 * kc][3], addr);
            uint32_t addr2 = addr + 32;
            ldsm_x4(aq[2 * kc + 1][0], aq[2 * kc + 1][1],
                    aq[2 * kc + 1][2], aq[2 * kc + 1][3], addr2);
        }
    }
    __syncthreads();   // all warps done extracting Q before K overwrites Ks

    // issue K/V tile k0 into stage st
    #define FISSUE(st, k0) do {                                                        \
        _Pragma("unroll")                                                              \
        for (int p = 0; p < 2; ++p) {                                                  \
            int idx = tid + p * 256;                                                   \
            int r = idx >> 3, c = idx & 7;                                             \
            const __half* bp = qkvh + (size_t)(b * T_SEQ + (k0) + r) * 3072 + h * 64 + c * 8; \
            cp16(ksBase + (st) * FSTGB + r * 144 + c * 16, bp + 1024);                 \
            cp16(vsBase + (st) * FSTGB + r * 144 + c * 16, bp + 2048);                 \
        }                                                                              \
        CP_COMMIT();                                                                   \
    } while (0)

    FISSUE(0, 0);

    float oacc[8][4];
    #pragma unroll
    for (int i = 0; i < 8; ++i)
        #pragma unroll
        for (int j = 0; j < 4; ++j) oacc[i][j] = 0.0f;
    float mrow0 = -1e30f, mrow1 = -1e30f;
    float lrow0 = 0.0f,   lrow1 = 0.0f;

    const int nkt = 2 * qt + 2;
    for (int kt = 0; kt < nkt; ++kt) {
        const int k0 = kt * 64;

        __syncthreads();   // all warps done compute(kt-1): stage (kt+1)&1 free
        if (kt + 1 < nkt) { FISSUE((kt + 1) & 1, (kt + 1) * 64); CP_WAIT1(); }
        else              { CP_WAIT0(); }
        __syncthreads();   // stage kt&1 visible block-wide

        const uint32_t kss = ksBase + (kt & 1) * FSTGB;
        const uint32_t vss = vsBase + (kt & 1) * FSTGB;

        // ---- S = Q @ K^T ----
        float sacc[8][4];
        #pragma unroll
        for (int i = 0; i < 8; ++i)
            #pragma unroll
            for (int j = 0; j < 4; ++j) sacc[i][j] = 0.0f;

        #pragma unroll
        for (int n0 = 0; n0 < 8; ++n0) {
            #pragma unroll
            for (int dh = 0; dh < 2; ++dh) {
                uint32_t addr = kss + (n0 * 8 + k_tok8) * 144 + dh * 64 + k_doff;
                uint32_t r0, r1, r2, r3;
                ldsm_x4(r0, r1, r2, r3, addr);
                uint32_t bf0[2] = { r0, r1 };
                uint32_t bf1[2] = { r2, r3 };
                mma_f16(sacc[n0], aq[2 * dh],     bf0);
                mma_f16(sacc[n0], aq[2 * dh + 1], bf1);
            }
        }

        // ---- causal mask + row max (scale folded into Q) ----
        const int row0 = q0 + qrow + g;
        const int row1 = row0 + 8;
        const bool domask = (k0 + 63 > q0 + qrow);
        float ml0 = -1e30f, ml1 = -1e30f;
        #pragma unroll
        for (int n0 = 0; n0 < 8; ++n0) {
            const int c0 = k0 + n0 * 8 + 2 * tg;
            const int c1 = c0 + 1;
            float s0 = sacc[n0][0];
            float s1 = sacc[n0][1];
            float s2 = sacc[n0][2];
            float s3 = sacc[n0][3];
            if (domask) {
                if (c0 > row0) s0 = -1e30f;
                if (c1 > row0) s1 = -1e30f;
                if (c0 > row1) s2 = -1e30f;
                if (c1 > row1) s3 = -1e30f;
            }
            sacc[n0][0] = s0; sacc[n0][1] = s1;
            sacc[n0][2] = s2; sacc[n0][3] = s3;
            ml0 = fmaxf(ml0, fmaxf(s0, s1));
            ml1 = fmaxf(ml1, fmaxf(s2, s3));
        }
        ml0 = fmaxf(ml0, __shfl_xor_sync(0xffffffffu, ml0, 1));
        ml0 = fmaxf(ml0, __shfl_xor_sync(0xffffffffu, ml0, 2));
        ml1 = fmaxf(ml1, __shfl_xor_sync(0xffffffffu, ml1, 1));
        ml1 = fmaxf(ml1, __shfl_xor_sync(0xffffffffu, ml1, 2));

        const float nm0 = fmaxf(mrow0, ml0);
        const float nm1 = fmaxf(mrow1, ml1);
        const float al0 = __expf(mrow0 - nm0);
        const float al1 = __expf(mrow1 - nm1);
        mrow0 = nm0; mrow1 = nm1;

        float sum0 = 0.0f, sum1 = 0.0f;
        #pragma unroll
        for (int n0 = 0; n0 < 8; ++n0) {
            float p0 = __expf(sacc[n0][0] - nm0);
            float p1 = __expf(sacc[n0][1] - nm0);
            float p2 = __expf(sacc[n0][2] - nm1);
            float p3 = __expf(sacc[n0][3] - nm1);
            sacc[n0][0] = p0; sacc[n0][1] = p1;
            sacc[n0][2] = p2; sacc[n0][3] = p3;
            sum0 += p0 + p1;
            sum1 += p2 + p3;
        }
        sum0 += __shfl_xor_sync(0xffffffffu, sum0, 1);
        sum0 += __shfl_xor_sync(0xffffffffu, sum0, 2);
        sum1 += __shfl_xor_sync(0xffffffffu, sum1, 1);
        sum1 += __shfl_xor_sync(0xffffffffu, sum1, 2);
        lrow0 = lrow0 * al0 + sum0;
        lrow1 = lrow1 * al1 + sum1;

        #pragma unroll
        for (int n0 = 0; n0 < 8; ++n0) {
            oacc[n0][0] *= al0; oacc[n0][1] *= al0;
            oacc[n0][2] *= al1; oacc[n0][3] *= al1;
        }

        // ---- P: C-frag -> A-frag in registers ----
        uint32_t ap[4][4];
        #pragma unroll
        for (int kc = 0; kc < 4; ++kc) {
            ap[kc][0] = pack_f16x2(sacc[2 * kc][0],     sacc[2 * kc][1]);
            ap[kc][1] = pack_f16x2(sacc[2 * kc][2],     sacc[2 * kc][3]);
            ap[kc][2] = pack_f16x2(sacc[2 * kc + 1][0], sacc[2 * kc + 1][1]);
            ap[kc][3] = pack_f16x2(sacc[2 * kc + 1][2], sacc[2 * kc + 1][3]);
        }

        // ---- O += P @ V ----
        #pragma unroll
        for (int kc = 0; kc < 4; ++kc) {
            #pragma unroll
            for (int dp = 0; dp < 4; ++dp) {
                uint32_t addr = vss + (kc * 16 + v_tok) * 144 + (dp * 16 + v_dcol8) * 2;
                uint32_t r0, r1, r2, r3;
                ldsm_x4_t(r0, r1, r2, r3, addr);
                uint32_t bf0[2] = { r0, r1 };
                uint32_t bf1[2] = { r2, r3 };
                mma_f16(oacc[2 * dp],     ap[kc], bf0);
                mma_f16(oacc[2 * dp + 1], ap[kc], bf1);
            }
        }
    }
    #undef FISSUE

    // ---- epilogue: normalize, write fp16 [B*T, D_MODEL] ----
    const float li0 = 1.0f / lrow0;
    const float li1 = 1.0f / lrow1;
    __half* atth = g_atth;
    const size_t grow0 = (size_t)(b * T_SEQ + q0 + qrow + g);
    const size_t grow1 = grow0 + 8;
    #pragma unroll
    for (int n0 = 0; n0 < 8; ++n0) {
        const int col = h * 64 + n0 * 8 + 2 * tg;
        *(uint32_t*)(atth + grow0 * D_MODEL + col) =
            pack_f16x2(oacc[n0][0] * li0, oacc[n0][1] * li0);
        *(uint32_t*)(atth + grow1 * D_MODEL + col) =
            pack_f16x2(oacc[n0][2] * li1, oacc[n0][3] * li1);
    }
}

// ---------------------------------------------------------------------------
// Harness entry. Inputs: x, w_qkv, b_qkv, w_out, b_out (all fp32).
// ---------------------------------------------------------------------------
extern "C" void kernel_launch(void* const* d_in, const int* in_sizes, int n_in,
                              void* d_out, int out_size)
{
    (void)in_sizes; (void)n_in; (void)out_size;
    const float* x     = (const float*)d_in[0];
    const float* w_qkv = (const float*)d_in[1];
    const float* b_qkv = (const float*)d_in[2];
    const float* w_out = (const float*)d_in[3];
    const float* b_out = (const float*)d_in[4];
    float* out = (float*)d_out;

    __half *xh, *wqh, *woh, *qkvh, *atth;
    cudaGetSymbolAddress((void**)&xh,   g_xh);
    cudaGetSymbolAddress((void**)&wqh,  g_wqh);
    cudaGetSymbolAddress((void**)&woh,  g_woh);
    cudaGetSymbolAddress((void**)&qkvh, g_qkvh);
    cudaGetSymbolAddress((void**)&atth, g_atth);

    // 0) fp32 -> fp16 pre-conversion (one-time per launch)
    {
        const int nx = N_TOK * D_MODEL / 4;
        const int nw = D_MODEL * 3 * D_MODEL / 4;
        const int no = D_MODEL * D_MODEL / 4;
        cvt_f32_f16_kernel<<<(nx + 255) / 256, 256>>>((const float4*)x,     (uint2*)xh,  nx);
        cvt_f32_f16_kernel<<<(nw + 255) / 256, 256>>>((const float4*)w_qkv, (uint2*)wqh, nw);
        cvt_f32_f16_kernel<<<(no + 255) / 256, 256>>>((const float4*)w_out, (uint2*)woh, no);
    }

    // 1) QKV projection (fp16 out, Q columns pre-scaled by 1/8)
    gemm_f16_kernel<N_TOK, 3 * D_MODEL, D_MODEL, 1>
        <<<dim3((3 * D_MODEL) / 128, N_TOK / 128), 256>>>(xh, wqh, b_qkv, qkvh, D_MODEL);

    // 2) causal flash attention -> g_atth (fp16), Q-tile 128
    flash_attn_f16_kernel<<<dim3(T_SEQ / 128, N_HEADS, B_SZ), 256>>>();

    // 3) output projection (fp32 out)
    gemm_f16_kernel<N_TOK, D_MODEL, D_MODEL, 0>
        <<<dim3(D_MODEL / 128, N_TOK / 128), 256>>>(atth, woh, b_out, out, 0);
}

// round 16
// speedup vs baseline: 1.0669x; 1.0669x over previous
#include <cuda_runtime.h>
#include <cuda_fp16.h>
#include <cstdint>

#define T_SEQ   2048
#define D_MODEL 1024
#define N_HEADS 16
#define D_HEAD  64
#define B_SZ    2
#define N_TOK   (B_SZ * T_SEQ)   // 4096

// fp16 scratch (device globals: allocation-free per harness rules)
__device__ __half g_xh  [(size_t)N_TOK * D_MODEL];        // x in fp16
__device__ __half g_wqh [(size_t)D_MODEL * 3 * D_MODEL];  // w_qkv fp16
__device__ __half g_woh [(size_t)D_MODEL * D_MODEL];      // w_out fp16
__device__ __half g_qkvh[(size_t)N_TOK * 3 * D_MODEL];    // qkv (Q pre-scaled 1/8)
__device__ __half g_atth[(size_t)N_TOK * D_MODEL];        // attention out fp16

// ---------------------------------------------------------------------------
// helpers
// ---------------------------------------------------------------------------
__device__ __forceinline__ uint32_t pack_f16x2(float lo, float hi) {
    uint32_t r;
    asm("cvt.rn.f16x2.f32 %0, %1, %2;" : "=r"(r) : "f"(hi), "f"(lo));
    return r;
}

__device__ __forceinline__ void mma_f16(float c[4], const uint32_t a[4], const uint32_t b[2]) {
    asm volatile(
        "mma.sync.aligned.m16n8k16.row.col.f32.f16.f16.f32 "
        "{%0,%1,%2,%3}, {%4,%5,%6,%7}, {%8,%9}, {%0,%1,%2,%3};\n"
        : "+f"(c[0]), "+f"(c[1]), "+f"(c[2]), "+f"(c[3])
        : "r"(a[0]), "r"(a[1]), "r"(a[2]), "r"(a[3]), "r"(b[0]), "r"(b[1]));
}

__device__ __forceinline__ uint32_t smem_u32(const void* p) {
    uint32_t a;
    asm("{ .reg .u64 t; cvta.to.shared.u64 t, %1; cvt.u32.u64 %0, t; }"
        : "=r"(a) : "l"(p));
    return a;
}

__device__ __forceinline__ void ldsm_x4(uint32_t& r0, uint32_t& r1,
                                        uint32_t& r2, uint32_t& r3, uint32_t addr) {
    asm volatile("ldmatrix.sync.aligned.m8n8.x4.shared.b16 {%0,%1,%2,%3}, [%4];"
                 : "=r"(r0), "=r"(r1), "=r"(r2), "=r"(r3) : "r"(addr));
}
__device__ __forceinline__ void ldsm_x4_t(uint32_t& r0, uint32_t& r1,
                                          uint32_t& r2, uint32_t& r3, uint32_t addr) {
    asm volatile("ldmatrix.sync.aligned.m8n8.x4.trans.shared.b16 {%0,%1,%2,%3}, [%4];"
                 : "=r"(r0), "=r"(r1), "=r"(r2), "=r"(r3) : "r"(addr));
}

__device__ __forceinline__ void cp16(uint32_t dst, const void* src) {
    asm volatile("cp.async.cg.shared.global [%0], [%1], 16;" :: "r"(dst), "l"(src));
}
#define CP_COMMIT() asm volatile("cp.async.commit_group;" ::: "memory")
#define CP_WAIT0()  asm volatile("cp.async.wait_group 0;" ::: "memory")
#define CP_WAIT1()  asm volatile("cp.async.wait_group 1;" ::: "memory")

// ---------------------------------------------------------------------------
// fp32 -> fp16 converter (elementwise, float4 -> 2x f16x2)
// ---------------------------------------------------------------------------
__global__ void cvt_f32_f16_kernel(const float4* __restrict__ in,
                                   uint2* __restrict__ out, int n4)
{
    int i = blockIdx.x * blockDim.x + threadIdx.x;
    if (i < n4) {
        float4 v = in[i];
        out[i] = make_uint2(pack_f16x2(v.x, v.y), pack_f16x2(v.z, v.w));
    }
}

// ---------------------------------------------------------------------------
// fp16-in tensor-core GEMM with fused bias, 3-stage cp.async pipeline.
// (unchanged from round 14)
// ---------------------------------------------------------------------------
#define GWA 12   // A row stride in words (48B)
#define GWB 68   // B row stride in words (272B)

template <int M, int N, int K, int OUTH>
__global__ void __launch_bounds__(256, 2) gemm_f16_kernel(
    const __half* __restrict__ A, const __half* __restrict__ B,
    const float* __restrict__ bias, void* __restrict__ Cout, int q_cols)
{
    __shared__ __align__(16) uint32_t As[3][128 * GWA];
    __shared__ __align__(16) uint32_t Bs[3][16 * GWB];

    const int tid  = threadIdx.x;
    const int warp = tid >> 5;
    const int lane = tid & 31;
    const int g    = lane >> 2;
    const int tg   = lane & 3;
    const int wm   = (warp >> 1) * 32;
    const int wn   = (warp & 1) * 64;

    const int bm = blockIdx.y;
    const int bn = blockIdx.x;

    const __half* Ab = A + (size_t)bm * 128 * K;
    const __half* Bb = B + (size_t)bn * 128;

    const int a_r = tid >> 1, a_c = tid & 1;
    const int b_r = tid >> 4, b_c = tid & 15;

    float acc[2][8][4];
    #pragma unroll
    for (int i = 0; i < 2; ++i)
        #pragma unroll
        for (int j = 0; j < 8; ++j)
            #pragma unroll
            for (int q = 0; q < 4; ++q) acc[i][j][q] = 0.0f;

    const int a_row   = (lane & 7) + ((lane >> 3) & 1) * 8;
    const int a_chunk = (lane >> 4) & 1;
    const int b_k     = (lane & 7) + ((lane >> 3) & 1) * 8;
    const int b_nc8   = ((lane >> 4) & 1) * 8;

    const int NKT = K / 16;

    #define GISSUE(st, kt) do {                                                   \
        uint32_t ad = smem_u32(&As[st][0]) + a_r * 48 + a_c * 16;                 \
        cp16(ad, Ab + (size_t)a_r * K + (kt) + a_c * 8);                          \
        uint32_t bd = smem_u32(&Bs[st][0]) + b_r * 272 + b_c * 16;                \
        cp16(bd, Bb + (size_t)((kt) + b_r) * N + b_c * 8);                        \
        CP_COMMIT();                                                              \
    } while (0)

    GISSUE(0, 0);
    GISSUE(1, 16);

    for (int kt = 0; kt < NKT; ++kt) {
        const int cur = kt % 3;
        if (kt + 1 < NKT) CP_WAIT1(); else CP_WAIT0();
        __syncthreads();
        if (kt + 2 < NKT) GISSUE((kt + 2) % 3, (kt + 2) * 16);

        const uint32_t aBase = smem_u32(&As[cur][0]);
        const uint32_t bBase = smem_u32(&Bs[cur][0]);
        uint32_t a[2][4], b[8][2];
        #pragma unroll
        for (int mm = 0; mm < 2; ++mm) {
            uint32_t addr = aBase + (wm + mm * 16 + a_row) * 48 + a_chunk * 16;
            ldsm_x4(a[mm][0], a[mm][1], a[mm][2], a[mm][3], addr);
        }
        #pragma unroll
        for (int nc = 0; nc < 4; ++nc) {
            uint32_t addr = bBase + b_k * 272 + (wn + nc * 16 + b_nc8) * 2;
            uint32_t r0, r1, r2, r3;
            ldsm_x4_t(r0, r1, r2, r3, addr);
            b[2 * nc][0]     = r0; b[2 * nc][1]     = r1;
            b[2 * nc + 1][0] = r2; b[2 * nc + 1][1] = r3;
        }
        #pragma unroll
        for (int mm = 0; mm < 2; ++mm)
            #pragma unroll
            for (int nn = 0; nn < 8; ++nn)
                mma_f16(acc[mm][nn], a[mm], b[nn]);
    }
    #undef GISSUE

    #pragma unroll
    for (int mm = 0; mm < 2; ++mm) {
        const int r0 = bm * 128 + wm + mm * 16 + g;
        #pragma unroll
        for (int nn = 0; nn < 8; ++nn) {
            const int c0g = bn * 128 + wn + nn * 8 + 2 * tg;
            float b0 = bias[c0g], b1 = bias[c0g + 1];
            if (OUTH) {
                __half* C = (__half*)Cout;
                float sc = (c0g < q_cols) ? 0.125f : 1.0f;
                *(uint32_t*)(C + (size_t)r0 * N + c0g) =
                    pack_f16x2((acc[mm][nn][0] + b0) * sc, (acc[mm][nn][1] + b1) * sc);
                *(uint32_t*)(C + (size_t)(r0 + 8) * N + c0g) =
                    pack_f16x2((acc[mm][nn][2] + b0) * sc, (acc[mm][nn][3] + b1) * sc);
            } else {
                float* C = (float*)Cout;
                *(float2*)(C + (size_t)r0 * N + c0g) =
                    make_float2(acc[mm][nn][0] + b0, acc[mm][nn][1] + b1);
                *(float2*)(C + (size_t)(r0 + 8) * N + c0g) =
                    make_float2(acc[mm][nn][2] + b0, acc[mm][nn][3] + b1);
            }
        }
    }
}

// ---------------------------------------------------------------------------
// Causal flash attention, fp16 m16n8k16, ldmatrix frags.
// Q-tile 64 (4 warps x 16 rows), K-tile 64, DH=64 — round-14 granularity.
// 2-stage double-buffered K/V via cp.async: loads for kt+1 overlap compute(kt).
// ---------------------------------------------------------------------------
#define FWS   36               // K/V row stride in words (144B)
#define FSTGB (64 * 144)       // stage size in bytes (9216)

__global__ void __launch_bounds__(128, 3) flash_attn_f16_kernel()
{
    __shared__ __align__(16) uint32_t Ks[2 * 64 * FWS];
    __shared__ __align__(16) uint32_t Vs[2 * 64 * FWS];

    const int tid  = threadIdx.x;
    const int warp = tid >> 5;           // 0..3
    const int lane = tid & 31;
    const int g    = lane >> 2;
    const int tg   = lane & 3;
    const int qt   = gridDim.x - 1 - blockIdx.x;   // long diagonals first
    const int h    = blockIdx.y;
    const int b    = blockIdx.z;
    const int q0   = qt * 64;
    const int qrow = warp * 16;

    const __half* qkvh = g_qkvh;
    const uint32_t ksBase = smem_u32(Ks);
    const uint32_t vsBase = smem_u32(Vs);

    // ldmatrix lane addressing
    const int k_tok8  = lane & 7;
    const int k_doff  = ((lane >> 3) & 3) * 16;
    const int v_tok   = (lane & 7) + ((lane >> 3) & 1) * 8;
    const int v_dcol8 = ((lane >> 4) & 1) * 8;

    // ---- stage Q (64 rows, pre-scaled) into Ks stage 0 via cp.async ----
    #pragma unroll
    for (int p = 0; p < 4; ++p) {
        int idx = tid + p * 128;           // 0..511
        int r = idx >> 3, c = idx & 7;     // row 0..63, 16B chunk
        cp16(ksBase + r * 144 + c * 16,
             qkvh + (size_t)(b * T_SEQ + q0 + r) * 3072 + h * 64 + c * 8);
    }
    CP_COMMIT(); CP_WAIT0();
    __syncthreads();

    uint32_t aq[4][4];
    #pragma unroll
    for (int kc = 0; kc < 2; ++kc) {
        uint32_t addr = ksBase + (qrow + v_tok) * 144 + kc * 64 + v_dcol8 * 2;
        ldsm_x4(aq[2 * kc][0], aq[2 * kc][1], aq[2 * kc][2], aq[2 * kc][3], addr);
        uint32_t addr2 = addr + 32;
        ldsm_x4(aq[2 * kc + 1][0], aq[2 * kc + 1][1],
                aq[2 * kc + 1][2], aq[2 * kc + 1][3], addr2);
    }
    __syncthreads();   // all warps done extracting Q before stage 0 is refilled

    // issue K/V tile k0 into stage st
    #define FISSUE(st, k0) do {                                                        \
        _Pragma("unroll")                                                              \
        for (int p = 0; p < 4; ++p) {                                                  \
            int idx = tid + p * 128;                                                   \
            int r = idx >> 3, c = idx & 7;                                             \
            const __half* bp = qkvh + (size_t)(b * T_SEQ + (k0) + r) * 3072 + h * 64 + c * 8; \
            cp16(ksBase + (st) * FSTGB + r * 144 + c * 16, bp + 1024);                 \
            cp16(vsBase + (st) * FSTGB + r * 144 + c * 16, bp + 2048);                 \
        }                                                                              \
        CP_COMMIT();                                                                   \
    } while (0)

    FISSUE(0, 0);

    float oacc[8][4];
    #pragma unroll
    for (int i = 0; i < 8; ++i)
        #pragma unroll
        for (int j = 0; j < 4; ++j) oacc[i][j] = 0.0f;
    float mrow0 = -1e30f, mrow1 = -1e30f;
    float lrow0 = 0.0f,   lrow1 = 0.0f;

    const int nkt = qt + 1;
    for (int kt = 0; kt < nkt; ++kt) {
        const int k0 = kt * 64;

        __syncthreads();   // all warps done compute(kt-1): stage (kt+1)&1 free
        if (kt + 1 < nkt) { FISSUE((kt + 1) & 1, (kt + 1) * 64); CP_WAIT1(); }
        else              { CP_WAIT0(); }
        __syncthreads();   // stage kt&1 visible block-wide

        const uint32_t kss = ksBase + (kt & 1) * FSTGB;
        const uint32_t vss = vsBase + (kt & 1) * FSTGB;

        // ---- S = Q @ K^T ----
        float sacc[8][4];
        #pragma unroll
        for (int i = 0; i < 8; ++i)
            #pragma unroll
            for (int j = 0; j < 4; ++j) sacc[i][j] = 0.0f;

        #pragma unroll
        for (int n0 = 0; n0 < 8; ++n0) {
            #pragma unroll
            for (int dh = 0; dh < 2; ++dh) {
                uint32_t addr = kss + (n0 * 8 + k_tok8) * 144 + dh * 64 + k_doff;
                uint32_t r0, r1, r2, r3;
                ldsm_x4(r0, r1, r2, r3, addr);
                uint32_t bf0[2] = { r0, r1 };
                uint32_t bf1[2] = { r2, r3 };
                mma_f16(sacc[n0], aq[2 * dh],     bf0);
                mma_f16(sacc[n0], aq[2 * dh + 1], bf1);
            }
        }

        // ---- causal mask + row max (scale folded into Q) ----
        const int row0 = q0 + qrow + g;
        const int row1 = row0 + 8;
        const bool domask = (k0 + 63 > q0 + qrow);
        float ml0 = -1e30f, ml1 = -1e30f;
        #pragma unroll
        for (int n0 = 0; n0 < 8; ++n0) {
            const int c0 = k0 + n0 * 8 + 2 * tg;
            const int c1 = c0 + 1;
            float s0 = sacc[n0][0];
            float s1 = sacc[n0][1];
            float s2 = sacc[n0][2];
            float s3 = sacc[n0][3];
            if (domask) {
                if (c0 > row0) s0 = -1e30f;
                if (c1 > row0) s1 = -1e30f;
                if (c0 > row1) s2 = -1e30f;
                if (c1 > row1) s3 = -1e30f;
            }
            sacc[n0][0] = s0; sacc[n0][1] = s1;
            sacc[n0][2] = s2; sacc[n0][3] = s3;
            ml0 = fmaxf(ml0, fmaxf(s0, s1));
            ml1 = fmaxf(ml1, fmaxf(s2, s3));
        }
        ml0 = fmaxf(ml0, __shfl_xor_sync(0xffffffffu, ml0, 1));
        ml0 = fmaxf(ml0, __shfl_xor_sync(0xffffffffu, ml0, 2));
        ml1 = fmaxf(ml1, __shfl_xor_sync(0xffffffffu, ml1, 1));
        ml1 = fmaxf(ml1, __shfl_xor_sync(0xffffffffu, ml1, 2));

        const float nm0 = fmaxf(mrow0, ml0);
        const float nm1 = fmaxf(mrow1, ml1);
        const float al0 = __expf(mrow0 - nm0);
        const float al1 = __expf(mrow1 - nm1);
        mrow0 = nm0; mrow1 = nm1;

        float sum0 = 0.0f, sum1 = 0.0f;
        #pragma unroll
        for (int n0 = 0; n0 < 8; ++n0) {
            float p0 = __expf(sacc[n0][0] - nm0);
            float p1 = __expf(sacc[n0][1] - nm0);
            float p2 = __expf(sacc[n0][2] - nm1);
            float p3 = __expf(sacc[n0][3] - nm1);
            sacc[n0][0] = p0; sacc[n0][1] = p1;
            sacc[n0][2] = p2; sacc[n0][3] = p3;
            sum0 += p0 + p1;
            sum1 += p2 + p3;
        }
        sum0 += __shfl_xor_sync(0xffffffffu, sum0, 1);
        sum0 += __shfl_xor_sync(0xffffffffu, sum0, 2);
        sum1 += __shfl_xor_sync(0xffffffffu, sum1, 1);
        sum1 += __shfl_xor_sync(0xffffffffu, sum1, 2);
        lrow0 = lrow0 * al0 + sum0;
        lrow1 = lrow1 * al1 + sum1;

        #pragma unroll
        for (int n0 = 0; n0 < 8; ++n0) {
            oacc[n0][0] *= al0; oacc[n0][1] *= al0;
            oacc[n0][2] *= al1; oacc[n0][3] *= al1;
        }

        // ---- P: C-frag -> A-frag in registers ----
        uint32_t ap[4][4];
        #pragma unroll
        for (int kc = 0; kc < 4; ++kc) {
            ap[kc][0] = pack_f16x2(sacc[2 * kc][0],     sacc[2 * kc][1]);
            ap[kc][1] = pack_f16x2(sacc[2 * kc][2],     sacc[2 * kc][3]);
            ap[kc][2] = pack_f16x2(sacc[2 * kc + 1][0], sacc[2 * kc + 1][1]);
            ap[kc][3] = pack_f16x2(sacc[2 * kc + 1][2], sacc[2 * kc + 1][3]);
        }

        // ---- O += P @ V ----
        #pragma unroll
        for (int kc = 0; kc < 4; ++kc) {
            #pragma unroll
            for (int dp = 0; dp < 4; ++dp) {
                uint32_t addr = vss + (kc * 16 + v_tok) * 144 + (dp * 16 + v_dcol8) * 2;
                uint32_t r0, r1, r2, r3;
                ldsm_x4_t(r0, r1, r2, r3, addr);
                uint32_t bf0[2] = { r0, r1 };
                uint32_t bf1[2] = { r2, r3 };
                mma_f16(oacc[2 * dp],     ap[kc], bf0);
                mma_f16(oacc[2 * dp + 1], ap[kc], bf1);
            }
        }
    }
    #undef FISSUE

    // ---- epilogue: normalize, write fp16 [B*T, D_MODEL] ----
    const float li0 = 1.0f / lrow0;
    const float li1 = 1.0f / lrow1;
    __half* atth = g_atth;
    const size_t grow0 = (size_t)(b * T_SEQ + q0 + qrow + g);
    const size_t grow1 = grow0 + 8;
    #pragma unroll
    for (int n0 = 0; n0 < 8; ++n0) {
        const int col = h * 64 + n0 * 8 + 2 * tg;
        *(uint32_t*)(atth + grow0 * D_MODEL + col) =
            pack_f16x2(oacc[n0][0] * li0, oacc[n0][1] * li0);
        *(uint32_t*)(atth + grow1 * D_MODEL + col) =
            pack_f16x2(oacc[n0][2] * li1, oacc[n0][3] * li1);
    }
}

// ---------------------------------------------------------------------------
// Harness entry. Inputs: x, w_qkv, b_qkv, w_out, b_out (all fp32).
// ---------------------------------------------------------------------------
extern "C" void kernel_launch(void* const* d_in, const int* in_sizes, int n_in,
                              void* d_out, int out_size)
{
    (void)in_sizes; (void)n_in; (void)out_size;
    const float* x     = (const float*)d_in[0];
    const float* w_qkv = (const float*)d_in[1];
    const float* b_qkv = (const float*)d_in[2];
    const float* w_out = (const float*)d_in[3];
    const float* b_out = (const float*)d_in[4];
    float* out = (float*)d_out;

    __half *xh, *wqh, *woh, *qkvh, *atth;
    cudaGetSymbolAddress((void**)&xh,   g_xh);
    cudaGetSymbolAddress((void**)&wqh,  g_wqh);
    cudaGetSymbolAddress((void**)&woh,  g_woh);
    cudaGetSymbolAddress((void**)&qkvh, g_qkvh);
    cudaGetSymbolAddress((void**)&atth, g_atth);

    // 0) fp32 -> fp16 pre-conversion (one-time per launch)
    {
        const int nx = N_TOK * D_MODEL / 4;
        const int nw = D_MODEL * 3 * D_MODEL / 4;
        const int no = D_MODEL * D_MODEL / 4;
        cvt_f32_f16_kernel<<<(nx + 255) / 256, 256>>>((const float4*)x,     (uint2*)xh,  nx);
        cvt_f32_f16_kernel<<<(nw + 255) / 256, 256>>>((const float4*)w_qkv, (uint2*)wqh, nw);
        cvt_f32_f16_kernel<<<(no + 255) / 256, 256>>>((const float4*)w_out, (uint2*)woh, no);
    }

    // 1) QKV projection (fp16 out, Q columns pre-scaled by 1/8)
    gemm_f16_kernel<N_TOK, 3 * D_MODEL, D_MODEL, 1>
        <<<dim3((3 * D_MODEL) / 128, N_TOK / 128), 256>>>(xh, wqh, b_qkv, qkvh, D_MODEL);

    // 2) causal flash attention -> g_atth (fp16), Q-tile 64, pipelined K/V
    flash_attn_f16_kernel<<<dim3(T_SEQ / 64, N_HEADS, B_SZ), 128>>>();

    // 3) output projection (fp32 out)
    gemm_f16_kernel<N_TOK, D_MODEL, D_MODEL, 0>
        <<<dim3(D_MODEL / 128, N_TOK / 128), 256>>>(atth, woh, b_out, out, 0);
}